// round 1
// baseline (speedup 1.0000x reference)
#include <cuda_runtime.h>
#include <cstdint>

#define BATCH 2048
#define NCLS  1000
#define DIM   128
#define BM 64
#define BN 64
#define BK 64

// scratch (allocation-free rule: device globals)
__device__ float g_fn[BATCH];
__device__ float g_cn[NCLS];
__device__ int   g_is64;

// ---------------------------------------------------------------------------
// Detect label dtype width. If labels are int64 (values < 1000, nonnegative),
// every odd int32 word is 0. If labels are int32, the odd words are labels
// themselves and are all-zero with probability ~(1/1000)^1024.
// ---------------------------------------------------------------------------
__global__ void detect_kernel(const int* __restrict__ lab) {
    int any = 0;
    for (int i = threadIdx.x; i < BATCH / 2; i += blockDim.x)
        if (lab[2 * i + 1] != 0) any = 1;
    any = __syncthreads_or(any);
    if (threadIdx.x == 0) g_is64 = !any;
}

__device__ __forceinline__ int get_label(const void* lab, int b, int is64) {
    if (is64) return (int)(((const long long*)lab)[b]);
    return ((const int*)lab)[b];
}

// ---------------------------------------------------------------------------
// Row norms: one warp per row, one float4 per lane (DIM=128 = 32*4 exactly).
// Rows [0, BATCH) -> feat, rows [BATCH, BATCH+NCLS) -> centers.
// ---------------------------------------------------------------------------
__global__ void norms_kernel(const float* __restrict__ feat,
                             const float* __restrict__ centers) {
    int row  = blockIdx.x * (blockDim.x >> 5) + (threadIdx.x >> 5);
    int lane = threadIdx.x & 31;
    const float* src;
    float* dst;
    if (row < BATCH) {
        src = feat + (size_t)row * DIM;
        dst = g_fn + row;
    } else if (row < BATCH + NCLS) {
        int r = row - BATCH;
        src = centers + (size_t)r * DIM;
        dst = g_cn + r;
    } else {
        return;
    }
    float4 v = ((const float4*)src)[lane];
    float s = v.x * v.x + v.y * v.y + v.z * v.z + v.w * v.w;
#pragma unroll
    for (int o = 16; o; o >>= 1) s += __shfl_xor_sync(0xffffffffu, s, o);
    if (lane == 0) *dst = s;
}

// ---------------------------------------------------------------------------
// Main kernel: dist = fn + cn - 2*dot(f,c), logits = -0.5*dist,
// margin_logits = logits * (label==c ? 2 : 1).
// 64x64 tile per block, 256 threads, 4x4 microtile, K staged 64 at a time.
// smem is k-major so compute does LDS.128 on both operands.
// ---------------------------------------------------------------------------
__global__ void __launch_bounds__(256)
lgm_kernel(const float* __restrict__ feat,
           const void*  __restrict__ label,
           const float* __restrict__ centers,
           float* __restrict__ logits,
           float* __restrict__ mlogits) {
    __shared__ float sA[BK][BM];   // 16 KB
    __shared__ float sB[BK][BN];   // 16 KB

    const int tid = threadIdx.x;
    const int bb  = blockIdx.y * BM;
    const int cc  = blockIdx.x * BN;
    const int tx  = tid & 15;      // column group
    const int ty  = tid >> 4;      // row group

    float acc[4][4] = {};

    for (int kt = 0; kt < DIM; kt += BK) {
        // Stage A: 64 rows x 64 k (1024 float4). r = idx&63 => conflict-free
        // smem store banks; global loads are 16B per lane, every sector used.
#pragma unroll
        for (int i = 0; i < 4; i++) {
            int idx = tid + i * 256;
            int r   = idx & 63;
            int k4  = idx >> 6;
            float4 v = *(const float4*)(feat + (size_t)(bb + r) * DIM + kt + k4 * 4);
            sA[k4 * 4 + 0][r] = v.x;
            sA[k4 * 4 + 1][r] = v.y;
            sA[k4 * 4 + 2][r] = v.z;
            sA[k4 * 4 + 3][r] = v.w;
        }
        // Stage B with tail guard (C=1000 < 16*64)
#pragma unroll
        for (int i = 0; i < 4; i++) {
            int idx = tid + i * 256;
            int r   = idx & 63;
            int k4  = idx >> 6;
            int c   = cc + r;
            float4 v = make_float4(0.f, 0.f, 0.f, 0.f);
            if (c < NCLS)
                v = *(const float4*)(centers + (size_t)c * DIM + kt + k4 * 4);
            sB[k4 * 4 + 0][r] = v.x;
            sB[k4 * 4 + 1][r] = v.y;
            sB[k4 * 4 + 2][r] = v.z;
            sB[k4 * 4 + 3][r] = v.w;
        }
        __syncthreads();

#pragma unroll 8
        for (int k = 0; k < BK; k++) {
            float4 a = *(const float4*)&sA[k][ty * 4];
            float4 b = *(const float4*)&sB[k][tx * 4];
            acc[0][0] = fmaf(a.x, b.x, acc[0][0]);
            acc[0][1] = fmaf(a.x, b.y, acc[0][1]);
            acc[0][2] = fmaf(a.x, b.z, acc[0][2]);
            acc[0][3] = fmaf(a.x, b.w, acc[0][3]);
            acc[1][0] = fmaf(a.y, b.x, acc[1][0]);
            acc[1][1] = fmaf(a.y, b.y, acc[1][1]);
            acc[1][2] = fmaf(a.y, b.z, acc[1][2]);
            acc[1][3] = fmaf(a.y, b.w, acc[1][3]);
            acc[2][0] = fmaf(a.z, b.x, acc[2][0]);
            acc[2][1] = fmaf(a.z, b.y, acc[2][1]);
            acc[2][2] = fmaf(a.z, b.z, acc[2][2]);
            acc[2][3] = fmaf(a.z, b.w, acc[2][3]);
            acc[3][0] = fmaf(a.w, b.x, acc[3][0]);
            acc[3][1] = fmaf(a.w, b.y, acc[3][1]);
            acc[3][2] = fmaf(a.w, b.z, acc[3][2]);
            acc[3][3] = fmaf(a.w, b.w, acc[3][3]);
        }
        __syncthreads();
    }

    // Epilogue: dist -> logits / margin_logits. cb is a multiple of 4 and
    // NCLS is a multiple of 4, so the float4 store is either fully in or out.
    const int is64 = g_is64;
    const int rb = bb + ty * 4;
    const int cb = cc + tx * 4;
    if (cb < NCLS) {
        float cn0 = g_cn[cb + 0], cn1 = g_cn[cb + 1];
        float cn2 = g_cn[cb + 2], cn3 = g_cn[cb + 3];
#pragma unroll
        for (int i = 0; i < 4; i++) {
            int b_ = rb + i;
            float fn = g_fn[b_];
            int  lb = get_label(label, b_, is64);
            float4 lg;
            lg.x = -0.5f * (fn + cn0 - 2.f * acc[i][0]);
            lg.y = -0.5f * (fn + cn1 - 2.f * acc[i][1]);
            lg.z = -0.5f * (fn + cn2 - 2.f * acc[i][2]);
            lg.w = -0.5f * (fn + cn3 - 2.f * acc[i][3]);
            float4 ml = lg;
            if (lb == cb + 0) ml.x = 2.f * lg.x;
            if (lb == cb + 1) ml.y = 2.f * lg.y;
            if (lb == cb + 2) ml.z = 2.f * lg.z;
            if (lb == cb + 3) ml.w = 2.f * lg.w;
            size_t off = (size_t)b_ * NCLS + cb;
            *(float4*)(logits  + off) = lg;
            *(float4*)(mlogits + off) = ml;
        }
    }
}

// ---------------------------------------------------------------------------
// likelihood = -(1/B) * sum_b logits[b, label[b]]
// ---------------------------------------------------------------------------
__global__ void lik_kernel(const float* __restrict__ logits,
                           const void* __restrict__ label,
                           float* __restrict__ out) {
    __shared__ float red[256];
    const int is64 = g_is64;
    float s = 0.f;
    for (int b = threadIdx.x; b < BATCH; b += 256)
        s += logits[(size_t)b * NCLS + get_label(label, b, is64)];
    red[threadIdx.x] = s;
    __syncthreads();
    for (int o = 128; o; o >>= 1) {
        if (threadIdx.x < o) red[threadIdx.x] += red[threadIdx.x + o];
        __syncthreads();
    }
    if (threadIdx.x == 0) *out = -red[0] / (float)BATCH;
}

// ---------------------------------------------------------------------------
extern "C" void kernel_launch(void* const* d_in, const int* in_sizes, int n_in,
                              void* d_out, int out_size) {
    const float* feat    = (const float*)d_in[0];
    const void*  label   = d_in[1];
    const float* centers = (const float*)d_in[2];

    float* out     = (float*)d_out;
    float* logits  = out;                                // [B, C]
    float* mlogits = out + (size_t)BATCH * NCLS;         // [B, C]
    float* lik     = out + 2 * (size_t)BATCH * NCLS;     // scalar

    detect_kernel<<<1, 256>>>((const int*)label);

    int rows = BATCH + NCLS;
    int warps_per_block = 8;
    norms_kernel<<<(rows + warps_per_block - 1) / warps_per_block,
                   warps_per_block * 32>>>(feat, centers);

    dim3 grid((NCLS + BN - 1) / BN, BATCH / BM);  // (16, 32)
    lgm_kernel<<<grid, 256>>>(feat, label, centers, logits, mlogits);

    lik_kernel<<<1, 256>>>(logits, label, lik);
}

// round 3
// speedup vs baseline: 2.3112x; 2.3112x over previous
#include <cuda_runtime.h>
#include <cuda_bf16.h>
#include <cstdint>

#define BATCH 2048
#define NCLS  1000
#define DIM   128
#define TM 128
#define TN 128
#define ROWB 272            // smem row stride: 128 bf16 + 16B pad (conflict-free)

// deterministic likelihood partials (one per CTA)
__device__ float g_part[128];

// ---- smem byte offsets ----
#define OFF_A   0                       // A tile: 128 rows x 272B = 34816
#define OFF_B   (128 * ROWB)            // B tile: 34816
#define OFF_FNP (256 * ROWB)            // float[128][2] feat norm partials
#define OFF_CNP (OFF_FNP + 1024)        // float[128][2] center norm partials
#define OFF_FNC (OFF_CNP + 1024)        // float[128]  0.5*||f||^2
#define OFF_CNC (OFF_FNC + 512)         // float[128]  0.5*||c||^2
#define OFF_RED (OFF_CNC + 512)         // float[256]
#define SMEM_BYTES (OFF_RED + 1024)     // 73728

static __device__ __forceinline__ uint32_t smem_u32(const void* p) {
    uint32_t a;
    asm("{ .reg .u64 t; cvta.to.shared.u64 t, %1; cvt.u32.u64 %0, t; }"
        : "=r"(a) : "l"(p));
    return a;
}

static __device__ __forceinline__ int get_label(const void* lab, int b, int is64) {
    if (is64) return (int)(((const long long*)lab)[b]);
    return ((const int*)lab)[b];
}

static __device__ __forceinline__ uint32_t bf2(float x, float y) {
    __nv_bfloat162 v = __floats2bfloat162_rn(x, y);
    return *(uint32_t*)&v;
}

#define LDSM_X4(d, addr)                                                      \
    asm volatile("ldmatrix.sync.aligned.m8n8.x4.shared.b16 {%0,%1,%2,%3},[%4];" \
        : "=r"((d)[0]), "=r"((d)[1]), "=r"((d)[2]), "=r"((d)[3])              \
        : "r"(addr))

#define MMA16816(d, a, b0, b1)                                                \
    asm volatile("mma.sync.aligned.m16n8k16.row.col.f32.bf16.bf16.f32 "       \
        "{%0,%1,%2,%3}, {%4,%5,%6,%7}, {%8,%9}, {%0,%1,%2,%3};"               \
        : "+f"((d)[0]), "+f"((d)[1]), "+f"((d)[2]), "+f"((d)[3])              \
        : "r"((a)[0]), "r"((a)[1]), "r"((a)[2]), "r"((a)[3]),                 \
          "r"(b0), "r"(b1))

__global__ void __launch_bounds__(256, 1)
lgm_mma_kernel(const float* __restrict__ feat,
               const void*  __restrict__ label,
               const float* __restrict__ centers,
               float* __restrict__ logits,
               float* __restrict__ mlogits)
{
    extern __shared__ char smem[];
    const uint32_t sb = smem_u32(smem);
    const int tid = threadIdx.x;
    const int bb = blockIdx.y * TM;
    const int cc = blockIdx.x * TN;

    // ---------------- staging: f32 -> bf16 tiles + fused norms ----------------
    const int r = tid & 127;     // tile row
    const int h = tid >> 7;      // which 64-col half

    {   // A = feat (always in-bounds)
        const float4* src = (const float4*)(feat + (size_t)(bb + r) * DIM + h * 64);
        char* dst = smem + OFF_A + r * ROWB + h * 128;
        float s = 0.f;
#pragma unroll
        for (int j = 0; j < 8; j++) {
            float4 v0 = src[2 * j], v1 = src[2 * j + 1];
            s += v0.x * v0.x + v0.y * v0.y + v0.z * v0.z + v0.w * v0.w
               + v1.x * v1.x + v1.y * v1.y + v1.z * v1.z + v1.w * v1.w;
            uint4 p;
            p.x = bf2(v0.x, v0.y);
            p.y = bf2(v0.z, v0.w);
            p.z = bf2(v1.x, v1.y);
            p.w = bf2(v1.z, v1.w);
            *(uint4*)(dst + j * 16) = p;
        }
        ((float*)(smem + OFF_FNP))[r * 2 + h] = s;
    }
    {   // B = centers (zero-fill rows >= NCLS)
        const int crow = cc + r;
        const bool ok = crow < NCLS;
        const float4* src = (const float4*)(centers + (size_t)crow * DIM + h * 64);
        char* dst = smem + OFF_B + r * ROWB + h * 128;
        float s = 0.f;
#pragma unroll
        for (int j = 0; j < 8; j++) {
            float4 v0 = ok ? src[2 * j]     : make_float4(0.f, 0.f, 0.f, 0.f);
            float4 v1 = ok ? src[2 * j + 1] : make_float4(0.f, 0.f, 0.f, 0.f);
            s += v0.x * v0.x + v0.y * v0.y + v0.z * v0.z + v0.w * v0.w
               + v1.x * v1.x + v1.y * v1.y + v1.z * v1.z + v1.w * v1.w;
            uint4 p;
            p.x = bf2(v0.x, v0.y);
            p.y = bf2(v0.z, v0.w);
            p.z = bf2(v1.x, v1.y);
            p.w = bf2(v1.z, v1.w);
            *(uint4*)(dst + j * 16) = p;
        }
        ((float*)(smem + OFF_CNP))[r * 2 + h] = s;
    }

    // label dtype probe on global rows 0..127 ONLY (stays in-bounds for int32):
    // int64 labels < 1000  =>  all sampled high words zero
    int hw = 0;
    if (tid < 128) hw = (((const int*)label)[2 * tid + 1] != 0);
    const int is64 = !__syncthreads_or(hw);    // barrier also covers smem stores

    if (tid < 128) {
        const float* fnp = (const float*)(smem + OFF_FNP);
        const float* cnp = (const float*)(smem + OFF_CNP);
        ((float*)(smem + OFF_FNC))[tid] = 0.5f * (fnp[2 * tid] + fnp[2 * tid + 1]);
        ((float*)(smem + OFF_CNC))[tid] = 0.5f * (cnp[2 * tid] + cnp[2 * tid + 1]);
    }
    __syncthreads();

    // ---------------- HMMA mainloop ----------------
    const int wid  = tid >> 5;
    const int lane = tid & 31;
    const int wm = wid & 3;          // M group: rows wm*32..+31
    const int wn = wid >> 2;         // N group: cols wn*64..+63

    // ldmatrix lane addressing (identical scheme for A and B):
    // row = base + (lane & 15), 16B k-chunk = (lane >> 4)
    const uint32_t la = sb + OFF_A + (wm * 32 + (lane & 15)) * ROWB + (lane >> 4) * 16;
    const uint32_t lbm = sb + OFF_B + (wn * 64 + (lane & 15)) * ROWB + (lane >> 4) * 16;

    float acc[2][8][4] = {};
#pragma unroll
    for (int ks = 0; ks < 8; ks++) {
        const uint32_t ko = ks * 32;
        uint32_t a[2][4], b[4][4];
        LDSM_X4(a[0], la + ko);
        LDSM_X4(a[1], la + 16 * ROWB + ko);
#pragma unroll
        for (int nb = 0; nb < 4; nb++) LDSM_X4(b[nb], lbm + nb * 16 * ROWB + ko);
#pragma unroll
        for (int mi = 0; mi < 2; mi++)
#pragma unroll
            for (int nb = 0; nb < 4; nb++) {
                MMA16816(acc[mi][nb * 2 + 0], a[mi], b[nb][0], b[nb][2]);
                MMA16816(acc[mi][nb * 2 + 1], a[mi], b[nb][1], b[nb][3]);
            }
    }

    // ---------------- epilogue ----------------
    // D frag: {d0,d1}=row g cols tc*2..+1, {d2,d3}=row g+8
    const int g  = lane >> 2;
    const int tc = lane & 3;
    const float* fnc = (const float*)(smem + OFF_FNC);
    const float* cnc = (const float*)(smem + OFF_CNC);

    float lacc = 0.f;
#pragma unroll
    for (int mi = 0; mi < 2; mi++) {
#pragma unroll
        for (int rr = 0; rr < 2; rr++) {
            const int rloc = wm * 32 + mi * 16 + g + rr * 8;
            const int m = bb + rloc;
            const float fnh = fnc[rloc];
            const int lb = get_label(label, m, is64);
#pragma unroll
            for (int nf = 0; nf < 8; nf++) {
                const int cloc = wn * 64 + (nf >> 1) * 16 + (nf & 1) * 8 + tc * 2;
                const int c = cc + cloc;
                const float d0 = acc[mi][nf][rr * 2 + 0];
                const float d1 = acc[mi][nf][rr * 2 + 1];
                // logits = -0.5*dist = dot - 0.5||f||^2 - 0.5||c||^2
                const float lg0 = d0 - fnh - cnc[cloc];
                const float lg1 = d1 - fnh - cnc[cloc + 1];
                float ml0 = lg0, ml1 = lg1;
                if (lb == c)     { ml0 = 2.f * lg0; lacc += lg0; }
                if (lb == c + 1) { ml1 = 2.f * lg1; lacc += lg1; }
                if (c < NCLS) {
                    const size_t off = (size_t)m * NCLS + c;
                    *(float2*)(logits + off)  = make_float2(lg0, lg1);
                    *(float2*)(mlogits + off) = make_float2(ml0, ml1);
                }
            }
        }
    }

    // per-CTA likelihood partial (deterministic: no atomics)
    float* red = (float*)(smem + OFF_RED);
    red[tid] = lacc;
    __syncthreads();
#pragma unroll
    for (int o = 128; o > 0; o >>= 1) {
        if (tid < o) red[tid] += red[tid + o];
        __syncthreads();
    }
    if (tid == 0) g_part[blockIdx.y * 8 + blockIdx.x] = red[0];
}

// likelihood = -(1/B) * sum of partials; deterministic tree over fixed order
__global__ void finalize_kernel(float* __restrict__ lik) {
    __shared__ float s[128];
    const int t = threadIdx.x;
    s[t] = g_part[t];
    __syncthreads();
#pragma unroll
    for (int o = 64; o > 0; o >>= 1) {
        if (t < o) s[t] += s[t + o];
        __syncthreads();
    }
    if (t == 0) *lik = -s[0] * (1.f / (float)BATCH);
}

extern "C" void kernel_launch(void* const* d_in, const int* in_sizes, int n_in,
                              void* d_out, int out_size) {
    const float* feat    = (const float*)d_in[0];
    const void*  label   = d_in[1];
    const float* centers = (const float*)d_in[2];

    float* out     = (float*)d_out;
    float* logits  = out;                              // [B, C]
    float* mlogits = out + (size_t)BATCH * NCLS;       // [B, C]
    float* lik     = out + 2 * (size_t)BATCH * NCLS;   // scalar

    cudaFuncSetAttribute(lgm_mma_kernel,
                         cudaFuncAttributeMaxDynamicSharedMemorySize, SMEM_BYTES);

    dim3 grid(8, 16);   // 128 CTAs, one wave
    lgm_mma_kernel<<<grid, 256, SMEM_BYTES>>>(feat, label, centers, logits, mlogits);
    finalize_kernel<<<1, 128>>>(lik);
}